// round 1
// baseline (speedup 1.0000x reference)
#include <cuda_runtime.h>
#include <math.h>

// Problem constants (MILAttention: x[8,8192,768], gates FI=256)
#define BZ 8
#define PZ 8192
#define FZ 768
#define FI 256

// GEMM tiling
#define MT 64          // positions per block
#define KT 16          // k-tile
#define NTHREADS 256   // 32 i-groups x 8 p-groups

// Scratch for attention logits att[b,p]
__device__ float g_att[BZ * PZ];

// ---------------------------------------------------------------------------
// Fast, safe activations (error ~1e-6; saturate correctly at +-inf)
// ---------------------------------------------------------------------------
__device__ __forceinline__ float fast_tanh(float v) {
    // tanh(v) = 1 - 2/(exp(2v)+1); exp overflow -> +1, underflow -> -1
    float e = __expf(2.0f * v);
    return 1.0f - __fdividef(2.0f, 1.0f + e);
}
__device__ __forceinline__ float fast_sigmoid(float u) {
    float e = __expf(-u);
    return __fdividef(1.0f, 1.0f + e);
}

// ---------------------------------------------------------------------------
// Kernel 1: att[b,p] = w_b + sum_i w[i] * tanh(x.Vw[i]+Vb[i]) * sig(x.Uw[i]+Ub[i])
// Block: 64 positions x 256 gates, K tiled by 16. 128 fp32 accumulators/thread.
// ---------------------------------------------------------------------------
__global__ __launch_bounds__(NTHREADS, 1)
void mil_att_kernel(const float* __restrict__ x,
                    const float* __restrict__ Vw, const float* __restrict__ Vb,
                    const float* __restrict__ Uw, const float* __restrict__ Ub,
                    const float* __restrict__ ww, const float* __restrict__ wb)
{
    __shared__ float xs[KT][MT + 1];      // transposed x tile: [k][p], pad 65
    __shared__ float vs[FI][KT + 1];      // [i][k], pad 17 -> conflict-free reads
    __shared__ float us[FI][KT + 1];
    __shared__ float red[32][MT + 1];     // cross-ig reduction

    const int tid = threadIdx.x;
    const int pg  = tid & 7;              // p-group: p = pg + 8*jj (interleaved)
    const int ig  = tid >> 3;             // i-group: i = ig*8 + j
    const int row = tid >> 2;             // 0..63 (loader role)
    const int c4  = tid & 3;              // 0..3  (float4 column)
    const size_t p_base = (size_t)blockIdx.x * MT;

    float accv[8][8], accu[8][8];
    #pragma unroll
    for (int a = 0; a < 8; a++)
        #pragma unroll
        for (int c = 0; c < 8; c++) { accv[a][c] = 0.0f; accu[a][c] = 0.0f; }

    for (int kt = 0; kt < FZ; kt += KT) {
        // ---- load x tile (64 rows x 16 cols), store transposed ----
        {
            const float4 v = *reinterpret_cast<const float4*>(
                x + (p_base + (size_t)row) * FZ + kt + c4 * 4);
            xs[c4 * 4 + 0][row] = v.x;
            xs[c4 * 4 + 1][row] = v.y;
            xs[c4 * 4 + 2][row] = v.z;
            xs[c4 * 4 + 3][row] = v.w;
        }
        // ---- load V/U weight tiles (256 rows x 16 cols each) ----
        #pragma unroll
        for (int it = 0; it < 4; it++) {
            const int r = it * 64 + row;
            const float4 v = *reinterpret_cast<const float4*>(
                Vw + (size_t)r * FZ + kt + c4 * 4);
            vs[r][c4 * 4 + 0] = v.x; vs[r][c4 * 4 + 1] = v.y;
            vs[r][c4 * 4 + 2] = v.z; vs[r][c4 * 4 + 3] = v.w;
            const float4 u = *reinterpret_cast<const float4*>(
                Uw + (size_t)r * FZ + kt + c4 * 4);
            us[r][c4 * 4 + 0] = u.x; us[r][c4 * 4 + 1] = u.y;
            us[r][c4 * 4 + 2] = u.z; us[r][c4 * 4 + 3] = u.w;
        }
        __syncthreads();

        // ---- FFMA mainloop: 16 k-steps x (8x8x2) FMA ----
        #pragma unroll
        for (int k = 0; k < KT; k++) {
            float xr[8], vr[8], ur[8];
            #pragma unroll
            for (int jj = 0; jj < 8; jj++) xr[jj] = xs[k][pg + 8 * jj];
            #pragma unroll
            for (int j = 0; j < 8; j++) {
                vr[j] = vs[ig * 8 + j][k];
                ur[j] = us[ig * 8 + j][k];
            }
            #pragma unroll
            for (int jj = 0; jj < 8; jj++)
                #pragma unroll
                for (int j = 0; j < 8; j++) {
                    accv[jj][j] = fmaf(xr[jj], vr[j], accv[jj][j]);
                    accu[jj][j] = fmaf(xr[jj], ur[j], accu[jj][j]);
                }
        }
        __syncthreads();
    }

    // ---- epilogue: gate, weight, reduce over i ----
    float wr[8], vbr[8], ubr[8];
    #pragma unroll
    for (int j = 0; j < 8; j++) {
        const int i = ig * 8 + j;
        wr[j]  = ww[i];
        vbr[j] = Vb[i];
        ubr[j] = Ub[i];
    }
    #pragma unroll
    for (int jj = 0; jj < 8; jj++) {
        float s = 0.0f;
        #pragma unroll
        for (int j = 0; j < 8; j++) {
            const float gv = fast_tanh(accv[jj][j] + vbr[j]);
            const float gu = fast_sigmoid(accu[jj][j] + ubr[j]);
            s = fmaf(wr[j], gv * gu, s);
        }
        red[ig][pg + 8 * jj] = s;
    }
    __syncthreads();

    if (tid < MT) {
        float s = 0.0f;
        #pragma unroll
        for (int g = 0; g < 32; g++) s += red[g][tid];
        g_att[p_base + tid] = s + wb[0];
    }
}

// ---------------------------------------------------------------------------
// Kernel 2: per-bag masked softmax over 8192 positions. One block per bag.
// nonpad may be int32 or int64 on disk; detect (int64 -> odd int32 words == 0,
// real int32 values are >= 1 so this is unambiguous).
// ---------------------------------------------------------------------------
__global__ void mil_softmax_kernel(const int* __restrict__ np32,
                                   float* __restrict__ out)
{
    const int b   = blockIdx.x;
    const int tid = threadIdx.x;
    __shared__ float sd[1024];

    const bool is64 = ((np32[1] | np32[3] | np32[5] | np32[7]) == 0);
    const int n = is64 ? np32[2 * b] : np32[b];

    const float* a = g_att + (size_t)b * PZ;
    float* o = out + (size_t)b * PZ;

    // max over valid positions
    float lmax = -3.402823466e38f;
    for (int p = tid; p < PZ; p += 1024)
        if (p < n) lmax = fmaxf(lmax, a[p]);
    sd[tid] = lmax;
    __syncthreads();
    for (int s = 512; s > 0; s >>= 1) {
        if (tid < s) sd[tid] = fmaxf(sd[tid], sd[tid + s]);
        __syncthreads();
    }
    const float m = sd[0];
    __syncthreads();

    // exp + sum
    float lsum = 0.0f;
    for (int p = tid; p < PZ; p += 1024) {
        const float e = (p < n) ? __expf(a[p] - m) : 0.0f;
        o[p] = e;
        lsum += e;
    }
    sd[tid] = lsum;
    __syncthreads();
    for (int s = 512; s > 0; s >>= 1) {
        if (tid < s) sd[tid] += sd[tid + s];
        __syncthreads();
    }
    const float inv = 1.0f / sd[0];

    // normalize
    for (int p = tid; p < PZ; p += 1024)
        o[p] *= inv;
}

// ---------------------------------------------------------------------------
// kernel_launch: inputs in metadata order
//   0:x  1:nonpad  2:V_w  3:V_b  4:U_w  5:U_b  6:w_w  7:w_b
// ---------------------------------------------------------------------------
extern "C" void kernel_launch(void* const* d_in, const int* in_sizes, int n_in,
                              void* d_out, int out_size)
{
    const float* x  = (const float*)d_in[0];
    const int*   np = (const int*)  d_in[1];
    const float* Vw = (const float*)d_in[2];
    const float* Vb = (const float*)d_in[3];
    const float* Uw = (const float*)d_in[4];
    const float* Ub = (const float*)d_in[5];
    const float* ww = (const float*)d_in[6];
    const float* wb = (const float*)d_in[7];
    float* out = (float*)d_out;

    mil_att_kernel<<<(BZ * PZ) / MT, NTHREADS>>>(x, Vw, Vb, Uw, Ub, ww, wb);
    mil_softmax_kernel<<<BZ, 1024>>>(np, out);
}